// round 4
// baseline (speedup 1.0000x reference)
#include <cuda_runtime.h>

// NLSearch: vid0, vid1 (1,3,32,256,256) f32. Query grid 64x64 stride 4,
// patch 7x7, shift window 8x8 (offsets -4..3), K=7.
// Each CTA handles TWO horizontally adjacent queries (qw, qw+4).
// Output float32: [0,86016) dists (1,1,12288,7); [86016,344064) inds (..,7,3).

#define V1W 18        // staged v1 row width: cols qw-7 .. qw+10
#define V1_CSTR 253   // 14*18=252 padded to 253 (odd -> conflict-free)
#define V0W 13        // staged v0 row width: cols qw-3 .. qw+9
#define V0_CSTR 91    // 7*13 = 91 (odd -> conflict-free)

__device__ __forceinline__ int refl(int x) {
    x = x < 0 ? -x : x;
    return x > 255 ? 510 - x : x;
}

__global__ void __launch_bounds__(256, 5)
nls_kernel(const float* __restrict__ vid0,
           const float* __restrict__ vid1,
           float* __restrict__ out)
{
    __shared__ float v1s[32 * V1_CSTR]; // [c][rr*18+cc], rows qh-7..qh+6
    __shared__ float v0s[32 * V0_CSTR]; // [c][ii*13+jj], rows qh-3..qh+3
    __shared__ float sdist[2][64];

    const int b  = blockIdx.x;
    const int t  = b >> 11;            // / 2048
    const int r  = b & 2047;
    const int n  = r >> 5;
    const int vb = r & 31;
    const int qh = n << 2;
    const int qw = vb << 3;            // query 0 at qw, query 1 at qw+4

    const int tid  = threadIdx.x;
    const int lane = tid & 31;
    const int w    = tid >> 5;         // warp id = s0 index (s0 = w - 4)

    // ---- stage both tiles (reflect applied); 343 positions over 256 threads ----
    const size_t toff = (size_t)t * 32 * 65536;
    for (int pos = tid; pos < 252 + 91; pos += 256) {
        if (pos < 252) {
            int rr = pos / V1W;
            int cc = pos - rr * V1W;
            int hg = refl(qh - 7 + rr);
            int wg = refl(qw - 7 + cc);
            const float* src = vid1 + toff + (hg << 8) + wg;
            float* dst = v1s + rr * V1W + cc;
#pragma unroll
            for (int c = 0; c < 32; c++)
                dst[c * V1_CSTR] = src[c << 16];
        } else {
            int p2 = pos - 252;
            int ii = p2 / V0W;
            int jj = p2 - ii * V0W;
            int hg = refl(qh - 3 + ii);
            int wg = refl(qw - 3 + jj);
            const float* src = vid0 + toff + (hg << 8) + wg;
            float* dst = v0s + ii * V0W + jj;
#pragma unroll
            for (int c = 0; c < 32; c++)
                dst[c * V0_CSTR] = src[c << 16];
        }
    }
    __syncthreads();

    // ---- compute: warp w = shift row s0; lane = channel; q = query 0/1.
    // acc[s1] += v0[c][i][4q+j] * v1[c][w+i][4q+s1+j]
#pragma unroll
    for (int q = 0; q < 2; q++) {
        const float* a_base = v0s + lane * V0_CSTR + 4 * q;
        const float* b_base = v1s + lane * V1_CSTR + w * V1W + 4 * q;

        float acc[8];
#pragma unroll
        for (int s = 0; s < 8; s++) acc[s] = 0.f;

#pragma unroll
        for (int i = 0; i < 7; i++) {
            float a[7], bb[14];
            const float* ar = a_base + i * V0W;
            const float* br = b_base + i * V1W;
#pragma unroll
            for (int j = 0; j < 7; j++)  a[j]  = ar[j];
#pragma unroll
            for (int j = 0; j < 14; j++) bb[j] = br[j];
#pragma unroll
            for (int s = 0; s < 8; s++)
#pragma unroll
                for (int j = 0; j < 7; j++)
                    acc[s] = fmaf(a[j], bb[j + s], acc[s]);
        }

        // warp-reduce 8 partials (sum over channels)
#pragma unroll
        for (int s = 0; s < 8; s++) {
            float val = acc[s];
#pragma unroll
            for (int o = 16; o > 0; o >>= 1)
                val += __shfl_xor_sync(0xffffffffu, val, o);
            if (lane == 0) sdist[q][(w << 3) + s] = val;
        }
    }
    __syncthreads();

    // ---- top-7: warp 0 -> query 0, warp 1 -> query 1 ----
    if (w < 2) {
        const float* sd = sdist[w];
        float a0 = sd[lane];
        float a1 = sd[lane + 32];
        if (lane == 4) a1 += 1e30f;    // self shift idx 36 boosted for selection

        const int qwq = qw + 4 * w;
        const int qidx = t * 4096 + n * 64 + vb * 2 + w;
        float* dbase = out + (size_t)qidx * 7;
        float* ibase = out + 86016 + (size_t)qidx * 21;

#pragma unroll
        for (int k = 0; k < 7; k++) {
            float bv = (a0 >= a1) ? a0 : a1;
            int   bi = (a0 >= a1) ? lane : lane + 32;
#pragma unroll
            for (int o = 16; o > 0; o >>= 1) {
                float ov = __shfl_xor_sync(0xffffffffu, bv, o);
                int   oi = __shfl_xor_sync(0xffffffffu, bi, o);
                if (ov > bv || (ov == bv && oi < bi)) { bv = ov; bi = oi; }
            }
            if (bi == lane)      a0 = -3.4e38f;
            if (bi == lane + 32) a1 = -3.4e38f;
            if (lane == 0) {
                dbase[k] = sd[bi];
                int s0 = bi >> 3;
                int s1 = bi & 7;
                ibase[k * 3 + 0] = (float)t;
                ibase[k * 3 + 1] = (float)refl(qh  + s0 - 4);
                ibase[k * 3 + 2] = (float)refl(qwq + s1 - 4);
            }
        }
    }
}

extern "C" void kernel_launch(void* const* d_in, const int* in_sizes, int n_in,
                              void* d_out, int out_size)
{
    const float* vid0 = (const float*)d_in[0];
    const float* vid1 = (const float*)d_in[1];
    float* out = (float*)d_out;
    nls_kernel<<<6144, 256>>>(vid0, vid1, out);
}

// round 5
// speedup vs baseline: 1.0540x; 1.0540x over previous
#include <cuda_runtime.h>

// NLSearch: vid0, vid1 (1,3,32,256,256) f32. Query grid 64x64 stride 4,
// patch 7x7, shift window 8x8 (offsets -4..3), K=7.
// Output float32: [0,86016) dists (1,1,12288,7); [86016,344064) inds (..,7,3).

#define V1_RSTR 16    // v1 row stride (floats): 14 valid + 2 pad, 64B rows
#define V1_CSTR 228   // channel stride: 14*16=224 padded to 228 (lane*228%32=lane*4, conflict-free .128)
#define V0_RSTR 8     // v0 row stride: 7 valid + 1 pad
#define V0_CSTR 60    // 7*8=56 padded to 60 (lane*60%32=lane*28, conflict-free .128)

__device__ __forceinline__ int refl(int x) {
    x = x < 0 ? -x : x;
    return x > 255 ? 510 - x : x;
}

__global__ void __launch_bounds__(256, 5)
nls_kernel(const float* __restrict__ vid0,
           const float* __restrict__ vid1,
           float* __restrict__ out)
{
    __shared__ __align__(16) float v1s[32 * V1_CSTR]; // [c][rr*16+cc], rows qh-7..qh+6
    __shared__ __align__(16) float v0s[32 * V0_CSTR]; // [c][ii*8+jj],  rows qh-3..qh+3
    __shared__ float sdist[64];

    const int b = blockIdx.x;
    const int t = b >> 12;
    const int r = b & 4095;
    const int n = r >> 6;
    const int v = r & 63;
    const int qh = n << 2;
    const int qw = v << 2;

    const int tid  = threadIdx.x;
    const int lane = tid & 31;
    const int w    = tid >> 5;       // warp id = s0 index (s0 = w - 4)

    // ---- stage (reflect applied); thread->(element) fixed once, loop channels ----
    if (tid < 196) {
        int rr = tid / 14;
        int cc = tid - rr * 14;
        int hg = refl(qh - 7 + rr);
        int wg = refl(qw - 7 + cc);
        const float* src = vid1 + (size_t)t * 32 * 65536 + (hg << 8) + wg;
        float* dst = v1s + rr * V1_RSTR + cc;
#pragma unroll 8
        for (int c = 0; c < 32; c++)
            dst[c * V1_CSTR] = src[c << 16];
    } else if (tid < 196 + 49) {
        int idx = tid - 196;
        int ii = idx / 7;
        int jj = idx - ii * 7;
        int hg = refl(qh - 3 + ii);
        int wg = refl(qw - 3 + jj);
        const float* src = vid0 + (size_t)t * 32 * 65536 + (hg << 8) + wg;
        float* dst = v0s + ii * V0_RSTR + jj;
#pragma unroll 8
        for (int c = 0; c < 32; c++)
            dst[c * V0_CSTR] = src[c << 16];
    }
    __syncthreads();

    // ---- compute: warp w = shift row s0; lane = channel; loop i = patch row.
    // acc[s1] += v0[c][i][j] * v1[c][w+i][j+s1], scalar FFMA, vector LDS.128.
    const float* a_base = v0s + lane * V0_CSTR;
    const float* b_base = v1s + lane * V1_CSTR + w * V1_RSTR;

    float acc[8];
#pragma unroll
    for (int s = 0; s < 8; s++) acc[s] = 0.f;

#pragma unroll
    for (int i = 0; i < 7; i++) {
        const float4* br = (const float4*)(b_base + i * V1_RSTR);
        float4 b0 = br[0], b1 = br[1], b2 = br[2], b3 = br[3];
        const float4* ar = (const float4*)(a_base + i * V0_RSTR);
        float4 a0 = ar[0], a1 = ar[1];

        float a[7]  = {a0.x, a0.y, a0.z, a0.w, a1.x, a1.y, a1.z};
        float bb[14] = {b0.x, b0.y, b0.z, b0.w, b1.x, b1.y, b1.z, b1.w,
                        b2.x, b2.y, b2.z, b2.w, b3.x, b3.y};

#pragma unroll
        for (int s = 0; s < 8; s++)
#pragma unroll
            for (int j = 0; j < 7; j++)
                acc[s] = fmaf(a[j], bb[j + s], acc[s]);
    }

    // ---- warp-reduce 8 partials (sum over channels) ----
#pragma unroll
    for (int s = 0; s < 8; s++) {
        float val = acc[s];
#pragma unroll
        for (int o = 16; o > 0; o >>= 1)
            val += __shfl_xor_sync(0xffffffffu, val, o);
        if (lane == 0) sdist[(w << 3) + s] = val;
    }
    __syncthreads();

    // ---- top-7 (warp 0): value desc, index asc tie-break ----
    if (w == 0) {
        float a0 = sdist[lane];
        float a1 = sdist[lane + 32];
        if (lane == 4) a1 += 1e30f;   // self shift idx 36 boosted for selection

        const int q = t * 4096 + n * 64 + v;
        float* dbase = out + (size_t)q * 7;
        float* ibase = out + 86016 + (size_t)q * 21;

#pragma unroll
        for (int k = 0; k < 7; k++) {
            float bv = (a0 >= a1) ? a0 : a1;
            int   bi = (a0 >= a1) ? lane : lane + 32;
#pragma unroll
            for (int o = 16; o > 0; o >>= 1) {
                float ov = __shfl_xor_sync(0xffffffffu, bv, o);
                int   oi = __shfl_xor_sync(0xffffffffu, bi, o);
                if (ov > bv || (ov == bv && oi < bi)) { bv = ov; bi = oi; }
            }
            if (bi == lane)      a0 = -3.4e38f;
            if (bi == lane + 32) a1 = -3.4e38f;
            if (lane == 0) {
                dbase[k] = sdist[bi];
                int s0 = bi >> 3;
                int s1 = bi & 7;
                ibase[k * 3 + 0] = (float)t;
                ibase[k * 3 + 1] = (float)refl(qh + s0 - 4);
                ibase[k * 3 + 2] = (float)refl(qw + s1 - 4);
            }
        }
    }
}

extern "C" void kernel_launch(void* const* d_in, const int* in_sizes, int n_in,
                              void* d_out, int out_size)
{
    const float* vid0 = (const float*)d_in[0];
    const float* vid1 = (const float*)d_in[1];
    float* out = (float*)d_out;
    nls_kernel<<<12288, 256>>>(vid0, vid1, out);
}

// round 6
// speedup vs baseline: 1.1470x; 1.0882x over previous
#include <cuda_runtime.h>

// NLSearch: vid0, vid1 (1,3,32,256,256) f32. Query grid 64x64 stride 4,
// patch 7x7, shift window 8x8 (offsets -4..3), K=7.
// Block = 128 threads (4 warps); warp w computes shift rows 2w and 2w+1,
// streaming v1 rows once each with register-carried v0 rows.
// Output float32: [0,86016) dists (1,1,12288,7); [86016,344064) inds (..,7,3).

#define V1_CSTR 197   // 14*14=196 padded to 197 (odd -> conflict-free)
#define V0_CSTR 49    // 7*7 (odd -> conflict-free)

__device__ __forceinline__ int refl(int x) {
    x = x < 0 ? -x : x;
    return x > 255 ? 510 - x : x;
}

__global__ void __launch_bounds__(128, 7)
nls_kernel(const float* __restrict__ vid0,
           const float* __restrict__ vid1,
           float* __restrict__ out)
{
    __shared__ float v1s[32 * V1_CSTR]; // [c][rr*14+cc], rows qh-7..qh+6
    __shared__ float v0s[32 * V0_CSTR]; // [c][ii*7+jj],  rows qh-3..qh+3
    __shared__ float sdist[64];

    const int b = blockIdx.x;
    const int t = b >> 12;
    const int r = b & 4095;
    const int n = r >> 6;
    const int v = r & 63;
    const int qh = n << 2;
    const int qw = v << 2;

    const int tid  = threadIdx.x;
    const int lane = tid & 31;
    const int w    = tid >> 5;        // warp 0..3 -> shift rows 2w, 2w+1

    // ---- stage (reflect applied); 245 positions over 128 threads ----
    const size_t toff = (size_t)t * 32 * 65536;
    for (int pos = tid; pos < 245; pos += 128) {
        if (pos < 196) {
            int rr = pos / 14;
            int cc = pos - rr * 14;
            int hg = refl(qh - 7 + rr);
            int wg = refl(qw - 7 + cc);
            const float* src = vid1 + toff + (hg << 8) + wg;
            float* dst = v1s + pos;
#pragma unroll 8
            for (int c = 0; c < 32; c++)
                dst[c * V1_CSTR] = src[c << 16];
        } else {
            int idx = pos - 196;
            int ii = idx / 7;
            int jj = idx - ii * 7;
            int hg = refl(qh - 3 + ii);
            int wg = refl(qw - 3 + jj);
            const float* src = vid0 + toff + (hg << 8) + wg;
            float* dst = v0s + idx;
#pragma unroll 8
            for (int c = 0; c < 32; c++)
                dst[c * V0_CSTR] = src[c << 16];
        }
    }
    __syncthreads();

    // ---- compute: lane = channel; warp w owns shift rows s0a=2w, s0b=2w+1.
    // Stream b rows r = 2w .. 2w+7 once each:
    //   row r -> shift s0a at i=r-2w (a row i), shift s0b at i=r-2w-1 (prev a row).
    const float* a_base = v0s + lane * V0_CSTR;
    const float* b_base = v1s + lane * V1_CSTR + (2 * w) * 14;

    float acc0[8], acc1[8];
#pragma unroll
    for (int s = 0; s < 8; s++) { acc0[s] = 0.f; acc1[s] = 0.f; }

    float aPrev[7];
#pragma unroll
    for (int rr = 0; rr < 8; rr++) {
        float bb[14];
        const float* br = b_base + rr * 14;
#pragma unroll
        for (int j = 0; j < 14; j++) bb[j] = br[j];

        float aCur[7];
        if (rr <= 6) {
            const float* ar = a_base + rr * 7;
#pragma unroll
            for (int j = 0; j < 7; j++) aCur[j] = ar[j];
            // shift row s0a = 2w, patch row i = rr
#pragma unroll
            for (int s = 0; s < 8; s++)
#pragma unroll
                for (int j = 0; j < 7; j++)
                    acc0[s] = fmaf(aCur[j], bb[j + s], acc0[s]);
        }
        if (rr >= 1) {
            // shift row s0b = 2w+1, patch row i = rr-1 (a row carried in regs)
#pragma unroll
            for (int s = 0; s < 8; s++)
#pragma unroll
                for (int j = 0; j < 7; j++)
                    acc1[s] = fmaf(aPrev[j], bb[j + s], acc1[s]);
        }
        if (rr <= 6) {
#pragma unroll
            for (int j = 0; j < 7; j++) aPrev[j] = aCur[j];
        }
    }

    // ---- warp-reduce 16 partials (sum over the 32 channels) ----
#pragma unroll
    for (int s = 0; s < 8; s++) {
        float v0r = acc0[s];
        float v1r = acc1[s];
#pragma unroll
        for (int o = 16; o > 0; o >>= 1) {
            v0r += __shfl_xor_sync(0xffffffffu, v0r, o);
            v1r += __shfl_xor_sync(0xffffffffu, v1r, o);
        }
        if (lane == 0) {
            sdist[(2 * w) * 8 + s]     = v0r;
            sdist[(2 * w + 1) * 8 + s] = v1r;
        }
    }
    __syncthreads();

    // ---- top-7 (warp 0): value desc, index asc tie-break ----
    if (w == 0) {
        float a0 = sdist[lane];
        float a1 = sdist[lane + 32];
        if (lane == 4) a1 += 1e30f;   // self shift idx 36 boosted for selection

        const int q = t * 4096 + n * 64 + v;
        float* dbase = out + (size_t)q * 7;
        float* ibase = out + 86016 + (size_t)q * 21;

#pragma unroll
        for (int k = 0; k < 7; k++) {
            float bv = (a0 >= a1) ? a0 : a1;
            int   bi = (a0 >= a1) ? lane : lane + 32;
#pragma unroll
            for (int o = 16; o > 0; o >>= 1) {
                float ov = __shfl_xor_sync(0xffffffffu, bv, o);
                int   oi = __shfl_xor_sync(0xffffffffu, bi, o);
                if (ov > bv || (ov == bv && oi < bi)) { bv = ov; bi = oi; }
            }
            if (bi == lane)      a0 = -3.4e38f;
            if (bi == lane + 32) a1 = -3.4e38f;
            if (lane == 0) {
                dbase[k] = sdist[bi];
                int s0 = bi >> 3;
                int s1 = bi & 7;
                ibase[k * 3 + 0] = (float)t;
                ibase[k * 3 + 1] = (float)refl(qh + s0 - 4);
                ibase[k * 3 + 2] = (float)refl(qw + s1 - 4);
            }
        }
    }
}

extern "C" void kernel_launch(void* const* d_in, const int* in_sizes, int n_in,
                              void* d_out, int out_size)
{
    const float* vid0 = (const float*)d_in[0];
    const float* vid1 = (const float*)d_in[1];
    float* out = (float*)d_out;
    nls_kernel<<<12288, 128>>>(vid0, vid1, out);
}